// round 4
// baseline (speedup 1.0000x reference)
#include <cuda_runtime.h>
#include <cuda_bf16.h>

#define NS    150
#define BATCH 32
#define DIN   1024
#define DH    512
#define DOUT  256

#define L1_TILES (NS * (DH / 64))     // 1200
#define L2_TILES (NS * (DOUT / 64))   // 600
#define TOT_TILES (L1_TILES + L2_TILES)

// -------------------- scratch (no cudaMalloc allowed) --------------------
__device__ float g_sW1[DH * DIN];
__device__ float g_sW2[DOUT * DH];
__device__ float g_H[NS * BATCH * DH];
__device__ int   g_q;
__device__ int   g_done1[NS];

// -------------------- threefry2x32 (JAX-exact, frozen) --------------------
__device__ __forceinline__ void tf2x32(unsigned k0, unsigned k1,
                                       unsigned x0, unsigned x1,
                                       unsigned& o0, unsigned& o1)
{
    const unsigned ks2 = k0 ^ k1 ^ 0x1BD11BDAu;
    x0 += k0; x1 += k1;
#define TF_RND(r) { x0 += x1; x1 = __funnelshift_l(x1, x1, (r)); x1 ^= x0; }
    TF_RND(13) TF_RND(15) TF_RND(26) TF_RND(6)   x0 += k1;  x1 += ks2 + 1u;
    TF_RND(17) TF_RND(29) TF_RND(16) TF_RND(24)  x0 += ks2; x1 += k0  + 2u;
    TF_RND(13) TF_RND(15) TF_RND(26) TF_RND(6)   x0 += k0;  x1 += k1  + 3u;
    TF_RND(17) TF_RND(29) TF_RND(16) TF_RND(24)  x0 += k1;  x1 += ks2 + 4u;
    TF_RND(13) TF_RND(15) TF_RND(26) TF_RND(6)   x0 += ks2; x1 += k0  + 5u;
#undef TF_RND
    o0 = x0; o1 = x1;
}

__device__ __forceinline__ float bits_to_normal(unsigned bits)
{
    float f = __uint_as_float((bits >> 9) | 0x3f800000u) - 1.0f;
    float x = fmaf(f, 2.0f, -0.99999994f);

    float w = -__logf(fmaf(-x, x, 1.0f));
    float p;
    if (w < 5.0f) {
        w -= 2.5f;
        p = 2.81022636e-08f;
        p = fmaf(p, w, 3.43273939e-07f);
        p = fmaf(p, w, -3.5233877e-06f);
        p = fmaf(p, w, -4.39150654e-06f);
        p = fmaf(p, w, 0.00021858087f);
        p = fmaf(p, w, -0.00125372503f);
        p = fmaf(p, w, -0.00417768164f);
        p = fmaf(p, w, 0.246640727f);
        p = fmaf(p, w, 1.50140941f);
    } else {
        w = sqrtf(w) - 3.0f;
        p = -0.000200214257f;
        p = fmaf(p, w, 0.000100950558f);
        p = fmaf(p, w, 0.00134934322f);
        p = fmaf(p, w, -0.00367342844f);
        p = fmaf(p, w, 0.00573950773f);
        p = fmaf(p, w, -0.0076224613f);
        p = fmaf(p, w, 0.00943887047f);
        p = fmaf(p, w, 1.00167406f);
        p = fmaf(p, w, 2.83297682f);
    }
    return 1.41421356237f * (p * x);
}

__device__ __forceinline__ float tf_normal(unsigned k0, unsigned k1, unsigned e)
{
    unsigned o0, o1;
    tf2x32(k0, k1, 0u, e, o0, o1);
    return bits_to_normal(o0 ^ o1);
}

// 4 interleaved threefry chains -> ILP 4 on the ALU dependency chain.
__device__ __forceinline__ void tf_normal4(unsigned k0, unsigned k1, unsigned e,
                                           float r[4])
{
    const unsigned ks2 = k0 ^ k1 ^ 0x1BD11BDAu;
    unsigned a[4], b[4];
#pragma unroll
    for (int i = 0; i < 4; i++) { a[i] = k0; b[i] = (e + (unsigned)i) + k1; }

#define TF_R4(rr) _Pragma("unroll") \
    for (int i = 0; i < 4; i++) { a[i] += b[i]; b[i] = __funnelshift_l(b[i], b[i], (rr)); b[i] ^= a[i]; }
#define TF_INJ4(ka, kb, g) _Pragma("unroll") \
    for (int i = 0; i < 4; i++) { a[i] += (ka); b[i] += (kb) + (g); }

    TF_R4(13) TF_R4(15) TF_R4(26) TF_R4(6)   TF_INJ4(k1,  ks2, 1u)
    TF_R4(17) TF_R4(29) TF_R4(16) TF_R4(24)  TF_INJ4(ks2, k0,  2u)
    TF_R4(13) TF_R4(15) TF_R4(26) TF_R4(6)   TF_INJ4(k0,  k1,  3u)
    TF_R4(17) TF_R4(29) TF_R4(16) TF_R4(24)  TF_INJ4(k1,  ks2, 4u)
    TF_R4(13) TF_R4(15) TF_R4(26) TF_R4(6)   TF_INJ4(ks2, k0,  5u)
#undef TF_R4
#undef TF_INJ4

#pragma unroll
    for (int i = 0; i < 4; i++) r[i] = bits_to_normal(a[i] ^ b[i]);
}

// -------------------- packed f32x2 helpers --------------------
__device__ __forceinline__ unsigned long long ffma2(unsigned long long a,
                                                    unsigned long long b,
                                                    unsigned long long c)
{
    unsigned long long d;
    asm("fma.rn.f32x2 %0, %1, %2, %3;" : "=l"(d) : "l"(a), "l"(b), "l"(c));
    return d;
}
__device__ __forceinline__ float2 unpack2(unsigned long long d)
{
    unsigned lo, hi;
    asm("mov.b64 {%0, %1}, %2;" : "=r"(lo), "=r"(hi) : "l"(d));
    return make_float2(__uint_as_float(lo), __uint_as_float(hi));
}

// -------------------- prep: exp(v_W) + reset queue/counters --------------------
__global__ __launch_bounds__(256) void prep_kernel(const float* __restrict__ vW1,
                                                   const float* __restrict__ vW2)
{
    int i = blockIdx.x * 256 + threadIdx.x;
    if (i < DH * DIN)  g_sW1[i] = expf(vW1[i]);
    if (i < DOUT * DH) g_sW2[i] = expf(vW2[i]);
    if (i < NS)        g_done1[i] = 0;
    if (i == NS)       g_q = 0;
}

// -------------------- one fused 64-wide tile --------------------
// Out[n][b][c0..c0+63] = act(bias + sum_k X[b][k] * (mu[c][k] + eps*s[c][k]))
template<int K, int N, bool RELU>
__device__ __forceinline__ void tile64(
    int n, int c0,
    const float* __restrict__ Xn,
    const float* __restrict__ mu, const float* __restrict__ s,
    const float* __restrict__ mub, const float* __restrict__ vb,
    float* __restrict__ Out,
    unsigned wk0, unsigned wk1, unsigned bk0, unsigned bk1,
    float2 (&xs)[32][33], float (&ws)[32][66], float (&bs)[64])
{
    const int tid = threadIdx.x;
    const int b0 = (tid & 7) * 4;
    const int h0 = (tid >> 3) * 4;

    const int gr  = tid & 63;            // c-row this thread generates
    const int gk0 = (tid >> 6) * 16;     // k-segment base (16 k-values)

    if (tid < 64) {
        int c = c0 + tid;
        float eps = tf_normal(bk0, bk1, (unsigned)(n * N + c));
        bs[tid] = fmaf(eps, expf(vb[c]), mub[c]);
    }

    unsigned long long acc[4][2];
#pragma unroll
    for (int i = 0; i < 4; i++) { acc[i][0] = 0ull; acc[i][1] = 0ull; }

    const unsigned erow = (unsigned)(n * N + c0 + gr) * (unsigned)K + (unsigned)gk0;
    const float* muRow = mu + (long long)(c0 + gr) * K + gk0;
    const float* sRow  = s  + (long long)(c0 + gr) * K + gk0;

    for (int k0 = 0; k0 < K; k0 += 32) {
        // ---- x tile (duplicated float2 for direct LDS.64 in FMA loop) ----
        {
            int idx = tid;
#pragma unroll
            for (int t = 0; t < 2; t++) {
                int r = idx >> 3, c4 = idx & 7;
                float4 xv = *reinterpret_cast<const float4*>(Xn + r * K + k0 + c4 * 4);
                xs[c4 * 4 + 0][r] = make_float2(xv.x, xv.x);
                xs[c4 * 4 + 1][r] = make_float2(xv.y, xv.y);
                xs[c4 * 4 + 2][r] = make_float2(xv.z, xv.z);
                xs[c4 * 4 + 3][r] = make_float2(xv.w, xv.w);
                idx += 128;
            }
        }
        // ---- generate 64c x 32k weight tile: 4 quads/thread ----
#pragma unroll
        for (int q = 0; q < 4; q++) {
            int kk = gk0 + q * 4;
            float r4[4];
            tf_normal4(wk0, wk1, erow + (unsigned)(k0 + q * 4), r4);
            float4 m  = *reinterpret_cast<const float4*>(muRow + k0 + q * 4);
            float4 sv = *reinterpret_cast<const float4*>(sRow  + k0 + q * 4);
            ws[kk + 0][gr] = fmaf(r4[0], sv.x, m.x);
            ws[kk + 1][gr] = fmaf(r4[1], sv.y, m.y);
            ws[kk + 2][gr] = fmaf(r4[2], sv.z, m.z);
            ws[kk + 3][gr] = fmaf(r4[3], sv.w, m.w);
        }
        __syncthreads();

        // ---- packed-f32x2 FMA ----
#pragma unroll 4
        for (int kk = 0; kk < 32; kk++) {
            unsigned long long xd[4], wd[2];
#pragma unroll
            for (int i = 0; i < 4; i++)
                xd[i] = *reinterpret_cast<const unsigned long long*>(&xs[kk][b0 + i]);
            wd[0] = *reinterpret_cast<const unsigned long long*>(&ws[kk][h0]);
            wd[1] = *reinterpret_cast<const unsigned long long*>(&ws[kk][h0 + 2]);
#pragma unroll
            for (int i = 0; i < 4; i++) {
                acc[i][0] = ffma2(xd[i], wd[0], acc[i][0]);
                acc[i][1] = ffma2(xd[i], wd[1], acc[i][1]);
            }
        }
        __syncthreads();
    }

#pragma unroll
    for (int j = 0; j < 2; j++) {
        float bj0 = bs[h0 + 2 * j];
        float bj1 = bs[h0 + 2 * j + 1];
#pragma unroll
        for (int i = 0; i < 4; i++) {
            float2 v = unpack2(acc[i][j]);
            v.x += bj0; v.y += bj1;
            if (RELU) { v.x = fmaxf(v.x, 0.0f); v.y = fmaxf(v.y, 0.0f); }
            *reinterpret_cast<float2*>(
                Out + ((long long)n * BATCH + (b0 + i)) * N + c0 + h0 + 2 * j) = v;
        }
    }
}

// -------------------- persistent worker: both layers via work queue --------------------
__global__ __launch_bounds__(128, 4) void persist_kernel(
    const float* __restrict__ x,
    const float* __restrict__ muW1, const float* __restrict__ mub1,
    const float* __restrict__ vb1,
    const float* __restrict__ muW2, const float* __restrict__ mub2,
    const float* __restrict__ vb2,
    float* __restrict__ out,
    unsigned k10, unsigned k11, unsigned k20, unsigned k21,
    unsigned k30, unsigned k31, unsigned k40, unsigned k41)
{
    __shared__ float2 xs[32][33];
    __shared__ float  ws[32][66];
    __shared__ float  bs[64];
    __shared__ int    s_item;

    for (;;) {
        if (threadIdx.x == 0) s_item = atomicAdd(&g_q, 1);
        __syncthreads();
        const int item = s_item;
        if (item >= TOT_TILES) break;

        if (item < L1_TILES) {
            const int n = item >> 3;                 // 8 tiles per sample
            const int c0 = (item & 7) * 64;
            tile64<DIN, DH, true>(n, c0, x, muW1, g_sW1, mub1, vb1, g_H,
                                  k10, k11, k20, k21, xs, ws, bs);
            __syncthreads();                         // all stores issued
            if (threadIdx.x == 0) {
                __threadfence();                     // release H writes
                atomicAdd(&g_done1[n], 1);
            }
        } else {
            const int i2 = item - L1_TILES;
            const int n = i2 >> 2;                   // 4 tiles per sample
            const int c0 = (i2 & 3) * 64;
            if (threadIdx.x == 0) {
                while (*(volatile int*)&g_done1[n] < 8) __nanosleep(64);
                __threadfence();                     // acquire H writes
            }
            __syncthreads();
            tile64<DH, DOUT, false>(n, c0, g_H + (long long)n * BATCH * DH,
                                    muW2, g_sW2, mub2, vb2, out,
                                    k30, k31, k40, k41, xs, ws, bs);
        }
        __syncthreads();                             // protect smem reuse
    }
}

// -------------------- host-side threefry for subkey derivation --------------------
static inline unsigned h_rotl(unsigned x, int r) { return (x << r) | (x >> (32 - r)); }
static void h_tf2x32(unsigned k0, unsigned k1, unsigned x0, unsigned x1,
                     unsigned& o0, unsigned& o1)
{
    const unsigned ks2 = k0 ^ k1 ^ 0x1BD11BDAu;
    x0 += k0; x1 += k1;
    static const int R[2][4] = {{13, 15, 26, 6}, {17, 29, 16, 24}};
    const unsigned ks[3] = {k0, k1, ks2};
    for (int g = 0; g < 5; g++) {
        for (int r = 0; r < 4; r++) {
            x0 += x1; x1 = h_rotl(x1, R[g & 1][r]); x1 ^= x0;
        }
        x0 += ks[(g + 1) % 3];
        x1 += ks[(g + 2) % 3] + (unsigned)(g + 1);
    }
    o0 = x0; o1 = x1;
}

extern "C" void kernel_launch(void* const* d_in, const int* in_sizes, int n_in,
                              void* d_out, int out_size)
{
    const float* x    = (const float*)d_in[0];
    const float* muW1 = (const float*)d_in[1];
    const float* mub1 = (const float*)d_in[2];
    const float* muW2 = (const float*)d_in[3];
    const float* mub2 = (const float*)d_in[4];
    const float* vW1  = (const float*)d_in[5];
    const float* vb1  = (const float*)d_in[6];
    const float* vW2  = (const float*)d_in[7];
    const float* vb2  = (const float*)d_in[8];
    float* out = (float*)d_out;

    unsigned keys[4][2];
    for (unsigned i = 0; i < 4; i++)
        h_tf2x32(0u, 42u, 0u, i, keys[i][0], keys[i][1]);

    static int nblocks = 0;
    if (nblocks == 0) {
        int sms = 148;
        cudaDeviceGetAttribute(&sms, cudaDevAttrMultiProcessorCount, 0);
        nblocks = sms * 4;                       // all resident (launch_bounds 4/SM)
        if (nblocks > TOT_TILES) nblocks = TOT_TILES;
    }

    prep_kernel<<<(DH * DIN + 255) / 256, 256>>>(vW1, vW2);

    persist_kernel<<<nblocks, 128>>>(
        x, muW1, mub1, vb1, muW2, mub2, vb2, out,
        keys[0][0], keys[0][1], keys[1][0], keys[1][1],
        keys[2][0], keys[2][1], keys[3][0], keys[3][1]);
}